// round 4
// baseline (speedup 1.0000x reference)
#include <cuda_runtime.h>
#include <cstdint>

// Problem constants (from reference_code)
#define DD    14
#define KK    2
#define BB    512
#define FF    512
#define NT    512
#define NF    1024
#define CELLS (BB * FF)          // 262144 (b,f) cells
#define PIX   (DD * DD)          // 196 pixels per cell
#define CPB   32                 // cells per block
#define THREADS 256
#define STRIDE 34                // float2 per cell region: cex[0..15], cey[16..31], pad 2
                                 // 34*8=272B -> 16B-aligned per-cell bases for LDS.128

__device__ __forceinline__ float ex2(float a) {
    float r;
    asm("ex2.approx.ftz.f32 %0, %1;" : "=f"(r) : "f"(a));
    return r;
}

// Block handles 32 consecutive (b,f) cells.
// Phase 1 (threads 0..63): thread (axis, cell) builds the 14-entry separable
//   table for both spots via an incremental recurrence in log2 space:
//   a(d) = lp2 - (d-c)^2 * s2,  s2 = log2e/(2 w^2),  lp2 = log2(h/(2 pi w^2))
//   (lp2 folded into the x-axis only). Constant 2nd difference -> 2 FADD + EX2 per entry.
// Phase 2 (8 warps x 4 cells): 49 float4 quads per cell, 2 rounds per cell.
//   Each quad: ex rows via 2x LDS.64, ey cols via 2x aligned LDS.128, 1x STG.128.
__global__ __launch_bounds__(THREADS) void gaussian_spot_kernel(
    const float* __restrict__ height,      // [K,B,F]
    const float* __restrict__ width,       // [K,B,F]
    const float* __restrict__ x,           // [K,B,F]
    const float* __restrict__ y,           // [K,B,F]
    const float* __restrict__ background,  // [B,F]
    const float* __restrict__ target_locs, // [NT,NF,2]
    const int*   __restrict__ n_idx,       // [B,1]
    const int*   __restrict__ f_arr,       // [F]
    float*       __restrict__ out)         // [1,B,F,D,D]
{
    __shared__ __align__(16) float2 tab[CPB * STRIDE];
    __shared__ float bgs[CPB];

    const int t = threadIdx.x;
    const int blockbase = blockIdx.x * CPB;

    // ---------------- Phase 1: build tables (threads 0..63) ----------------
    if (t < 2 * CPB) {
        const int lc   = t & (CPB - 1);
        const int axis = t >> 5;          // 0 = x/i-axis, 1 = y/j-axis
        const int cell = blockbase + lc;
        const int b = cell >> 9;          // / FF
        const int f = cell & (FF - 1);

        const int n  = n_idx[b];          // broadcast within block
        const int fi = f_arr[f];          // coalesced
        const float cloc = target_locs[((size_t)n * NF + (size_t)fi) * 2 + axis];
        if (axis == 0) bgs[lc] = background[cell];   // coalesced

        float a[KK], dl[KK], e2[KK];
#pragma unroll
        for (int k = 0; k < KK; k++) {
            const int off = k * CELLS + cell;        // coalesced loads
            const float h  = height[off];
            const float w  = width[off];
            const float sh = axis ? y[off] : x[off];
            const float c  = cloc + sh;              // spot center on this axis
            const float w2    = w * w;
            const float invw2 = __fdividef(1.0f, w2);
            const float s2    = 0.72134752044f * invw2;   // log2e / (2 w^2)
            const float lp2 = axis ? 0.0f
                                   : __log2f(h * 0.15915494309f * invw2);
            a[k]  = fmaf(-c * c, s2, lp2);           // a(0)
            dl[k] = (c + c - 1.0f) * s2;             // a(1)-a(0)
            e2[k] = s2 + s2;                         // -(2nd difference)
        }

        float2* trow = tab + lc * STRIDE + axis * 16;
#pragma unroll
        for (int d = 0; d < DD; d++) {
            trow[d] = make_float2(ex2(a[0]), ex2(a[1]));
            a[0] += dl[0]; dl[0] -= e2[0];
            a[1] += dl[1]; dl[1] -= e2[1];
        }
    }
    __syncthreads();

    // ---------------- Phase 2: emit pixels (8 warps x 4 cells each) --------
    const int warp = t >> 5;
    const int lane = t & 31;

    // Quad q covers pixels 4q..4q+3. Row i = 4q/14, col j = 4q%14 (always even).
    // Crossing into next row happens iff j == 12 (last 2 pixels -> row i+1, cols 0,1).
    int ir[2], jr[2], j2[2], qv[2];
    bool cross[2];
#pragma unroll
    for (int r = 0; r < 2; r++) {
        const int q  = r * 32 + lane;
        qv[r] = q;
        const int qq = (q < 49) ? q : 48;   // clamp for safe table indexing
        const int p0 = 4 * qq;
        ir[r] = p0 / 14;
        jr[r] = p0 - 14 * ir[r];
        cross[r] = (jr[r] == 12);
        j2[r] = cross[r] ? 0 : jr[r] + 2;
    }

#pragma unroll
    for (int cc = 0; cc < 4; cc++) {
        const int lc = warp * 4 + cc;
        const float bg = bgs[lc];
        const float2* cex = tab + lc * STRIDE;   // ex[i] (prefactor folded)
        const float2* cey = cex + 16;            // ey[j]
        float* outp = out + (size_t)(blockbase + lc) * PIX;
#pragma unroll
        for (int r = 0; r < 2; r++) {
            const float2 exa = cex[ir[r]];
            const float2 exb = cex[ir[r] + 1];        // only used when crossing
            const float4 eyab = *reinterpret_cast<const float4*>(cey + jr[r]); // ey[j], ey[j+1]
            const float4 eycd = *reinterpret_cast<const float4*>(cey + j2[r]); // ey[j2], ey[j2+1]
            const float2 exc = cross[r] ? exb : exa;

            float4 v;
            v.x = fmaf(exa.y, eyab.y, bg); v.x = fmaf(exa.x, eyab.x, v.x);
            v.y = fmaf(exa.y, eyab.w, bg); v.y = fmaf(exa.x, eyab.z, v.y);
            v.z = fmaf(exc.y, eycd.y, bg); v.z = fmaf(exc.x, eycd.x, v.z);
            v.w = fmaf(exc.y, eycd.w, bg); v.w = fmaf(exc.x, eycd.z, v.w);

            if (qv[r] < 49)
                *reinterpret_cast<float4*>(outp + 4 * qv[r]) = v;
        }
    }
}

extern "C" void kernel_launch(void* const* d_in, const int* in_sizes, int n_in,
                              void* d_out, int out_size)
{
    const float* height      = (const float*)d_in[0];
    const float* width       = (const float*)d_in[1];
    const float* x           = (const float*)d_in[2];
    const float* y           = (const float*)d_in[3];
    const float* background  = (const float*)d_in[4];
    const float* target_locs = (const float*)d_in[5];
    const int*   n_idx       = (const int*)d_in[6];
    const int*   f_arr       = (const int*)d_in[7];
    float*       out         = (float*)d_out;

    const int blocks = CELLS / CPB;   // 8192
    gaussian_spot_kernel<<<blocks, THREADS>>>(height, width, x, y, background,
                                              target_locs, n_idx, f_arr, out);
}